// round 6
// baseline (speedup 1.0000x reference)
#include <cuda_runtime.h>
#include <cuda_bf16.h>
#include <math_constants.h>
#include <cstdint>
#include <cstddef>

// Problem constants
#define BATCH   8
#define SEQ     1024
#define DIM     512
#define HEADS   8
#define DHEAD   64
#define MROWS   (BATCH * SEQ)        // 8192
#define LOCALB  16

// Scratch (device globals; allocation is forbidden)
__device__ float g_q[MROWS * DIM];    // head-split [b][h][s][d]
__device__ float g_k[MROWS * DIM];
__device__ float g_v[MROWS * DIM];
__device__ float g_att[MROWS * DIM];  // merged-head [b][s][h*64+d]

// ---------------------------------------------------------------------------
// tf32 tensor-core GEMM: C[M,512] = A[M,512] @ W[512,512] + bias
// Block tile 128x256, BK=16, double-buffered smem + register prefetch.
// 8 warps, each 64x64 (4x8 tiles of m16n8k8 tf32 mma).
// ---------------------------------------------------------------------------
#define BK 16
#define APITCH 20     // 20 mod 32: conflict-free for (g*20+tig)
#define BPITCH 264    // 264 mod 32 = 8: conflict-free for (tig*8+g)
#define AS_FLOATS (2 * 128 * APITCH)          // 5120
#define BS_FLOATS (2 * BK * BPITCH)           // 8448
#define GEMM_SMEM_BYTES ((AS_FLOATS + BS_FLOATS) * 4)   // 54272

__device__ __forceinline__ uint32_t f2tf32(float f) {
    uint32_t r;
    asm("cvt.rna.tf32.f32 %0, %1;" : "=r"(r) : "f"(f));
    return r;
}

__device__ __forceinline__ void mma_tf32(
    float& c0, float& c1, float& c2, float& c3,
    uint32_t a0, uint32_t a1, uint32_t a2, uint32_t a3,
    uint32_t b0, uint32_t b1)
{
    asm volatile(
        "mma.sync.aligned.m16n8k8.row.col.f32.tf32.tf32.f32 "
        "{%0,%1,%2,%3}, {%4,%5,%6,%7}, {%8,%9}, {%0,%1,%2,%3};"
        : "+f"(c0), "+f"(c1), "+f"(c2), "+f"(c3)
        : "r"(a0), "r"(a1), "r"(a2), "r"(a3), "r"(b0), "r"(b1));
}

__device__ __forceinline__ void gemm_tf32_body(
    const float* __restrict__ A, const float* __restrict__ W,
    const float* __restrict__ bias, float* __restrict__ C,
    int headsplit, int bx, int by)
{
    extern __shared__ float dynsmem[];
    float* As = dynsmem;                 // [2][128][APITCH]
    float* Bs = dynsmem + AS_FLOATS;     // [2][BK][BPITCH]
#define AS_AT(b, r, k) As[(b) * (128 * APITCH) + (r) * APITCH + (k)]
#define BS_AT(b, k, c) Bs[(b) * (BK * BPITCH) + (k) * BPITCH + (c)]

    const int tid  = threadIdx.x;
    const int warp = tid >> 5;
    const int lane = tid & 31;
    const int g    = lane >> 2;      // 0..7
    const int tig  = lane & 3;       // 0..3

    const int warp_m = warp >> 2;    // 0..1 -> rows warp_m*64
    const int warp_n = warp & 3;     // 0..3 -> cols warp_n*64

    const float* Aptr = A + (size_t)(by * 128) * DIM;
    const int n0 = bx * 256;

    // global-load mapping
    const int arow = tid >> 2;             // 0..63 (+64 second)
    const int ac4  = (tid & 3) * 4;
    const int bcol = (tid & 63) * 4;       // 0..252
    const int bk0  = tid >> 6;             // 0..3 (rows bk0+4i)

    float c[4][8][4];
#pragma unroll
    for (int i = 0; i < 4; i++)
#pragma unroll
        for (int j = 0; j < 8; j++)
#pragma unroll
            for (int r = 0; r < 4; r++) c[i][j][r] = 0.f;

    float4 ra0, ra1, rb[4];

    auto loadG = [&](int k0) {
        ra0 = *(const float4*)(Aptr + (size_t)arow * DIM + k0 + ac4);
        ra1 = *(const float4*)(Aptr + (size_t)(arow + 64) * DIM + k0 + ac4);
#pragma unroll
        for (int i = 0; i < 4; i++)
            rb[i] = *(const float4*)(W + (size_t)(k0 + bk0 + 4 * i) * DIM + n0 + bcol);
    };
    auto storeS = [&](int buf) {
        uint4 t;
        t.x = f2tf32(ra0.x); t.y = f2tf32(ra0.y); t.z = f2tf32(ra0.z); t.w = f2tf32(ra0.w);
        *(uint4*)&AS_AT(buf, arow, ac4) = t;
        t.x = f2tf32(ra1.x); t.y = f2tf32(ra1.y); t.z = f2tf32(ra1.z); t.w = f2tf32(ra1.w);
        *(uint4*)&AS_AT(buf, arow + 64, ac4) = t;
#pragma unroll
        for (int i = 0; i < 4; i++) {
            t.x = f2tf32(rb[i].x); t.y = f2tf32(rb[i].y);
            t.z = f2tf32(rb[i].z); t.w = f2tf32(rb[i].w);
            *(uint4*)&BS_AT(buf, bk0 + 4 * i, bcol) = t;
        }
    };

    loadG(0);
    storeS(0);
    __syncthreads();

    const int NIT = DIM / BK;   // 32
    for (int it = 0; it < NIT; ++it) {
        const int buf = it & 1;
        if (it + 1 < NIT) loadG((it + 1) * BK);

#pragma unroll
        for (int kk = 0; kk < 2; ++kk) {
            const int kb = kk * 8;
            uint32_t af[4][4];
#pragma unroll
            for (int mi = 0; mi < 4; mi++) {
                const int rb_ = warp_m * 64 + mi * 16;
                af[mi][0] = __float_as_uint(AS_AT(buf, rb_ + g,     kb + tig));
                af[mi][1] = __float_as_uint(AS_AT(buf, rb_ + g + 8, kb + tig));
                af[mi][2] = __float_as_uint(AS_AT(buf, rb_ + g,     kb + tig + 4));
                af[mi][3] = __float_as_uint(AS_AT(buf, rb_ + g + 8, kb + tig + 4));
            }
            uint32_t bf[8][2];
#pragma unroll
            for (int nj = 0; nj < 8; nj++) {
                const int cb = warp_n * 64 + nj * 8;
                bf[nj][0] = __float_as_uint(BS_AT(buf, kb + tig,     cb + g));
                bf[nj][1] = __float_as_uint(BS_AT(buf, kb + tig + 4, cb + g));
            }
#pragma unroll
            for (int mi = 0; mi < 4; mi++)
#pragma unroll
                for (int nj = 0; nj < 8; nj++)
                    mma_tf32(c[mi][nj][0], c[mi][nj][1], c[mi][nj][2], c[mi][nj][3],
                             af[mi][0], af[mi][1], af[mi][2], af[mi][3],
                             bf[nj][0], bf[nj][1]);
        }

        if (it + 1 < NIT) storeS((it + 1) & 1);
        __syncthreads();
    }

    // Epilogue
#pragma unroll
    for (int mi = 0; mi < 4; mi++) {
#pragma unroll
        for (int nj = 0; nj < 8; nj++) {
            const int cb = n0 + warp_n * 64 + nj * 8 + tig * 2;
#pragma unroll
            for (int half = 0; half < 2; half++) {
                const int row = by * 128 + warp_m * 64 + mi * 16 + g + half * 8;
                float v0 = c[mi][nj][half * 2 + 0] + bias[cb];
                float v1 = c[mi][nj][half * 2 + 1] + bias[cb + 1];
                if (headsplit) {
                    int b = row >> 10, s = row & 1023;
                    int h = cb >> 6,  d = cb & 63;
                    size_t o = ((size_t)((b * HEADS + h) * SEQ + s) << 6) + d;
                    C[o]     = v0;
                    C[o + 1] = v1;
                } else {
                    C[(size_t)row * DIM + cb]     = v0;
                    C[(size_t)row * DIM + cb + 1] = v1;
                }
            }
        }
    }
#undef AS_AT
#undef BS_AT
}

__global__ __launch_bounds__(256) void proj_qkv_kernel(
    const float* __restrict__ q,  const float* __restrict__ k,  const float* __restrict__ v,
    const float* __restrict__ Wq, const float* __restrict__ Wk, const float* __restrict__ Wv,
    const float* __restrict__ bq, const float* __restrict__ bk, const float* __restrict__ bv)
{
    const float* A; const float* W; const float* bias; float* C;
    if (blockIdx.z == 0)      { A = q; W = Wq; bias = bq; C = g_q; }
    else if (blockIdx.z == 1) { A = k; W = Wk; bias = bk; C = g_k; }
    else                      { A = v; W = Wv; bias = bv; C = g_v; }
    gemm_tf32_body(A, W, bias, C, 1, blockIdx.x, blockIdx.y);
}

__global__ __launch_bounds__(256) void out_proj_kernel(
    const float* __restrict__ Wo, const float* __restrict__ bo, float* __restrict__ out)
{
    gemm_tf32_body(g_att, Wo, bo, out, 0, blockIdx.x, blockIdx.y);
}

// ---------------------------------------------------------------------------
// Sparse attention, band-tiled + butterfly multi-reduce.
// 512 threads = 16 warps = 16 consecutive queries of one (b,h).
// Band+row logits (<=31) -> register partials p[32], one 31-shuffle
// multi-reduce puts logit n on lane n. Frame logits (<=3) via old path.
// ---------------------------------------------------------------------------
#define FULLMASK 0xffffffffu
#define AQ 16                         // queries per block
#define BANDROWS (AQ + LOCALB)        // 32

__global__ __launch_bounds__(512) void sparse_attn_kernel()
{
    __shared__ float Kb[BANDROWS][DHEAD];
    __shared__ float Vb[BANDROWS][DHEAD];

    const int warp = threadIdx.x >> 5;       // 0..15 = query offset
    const int lane = threadIdx.x & 31;
    const int s0   = (blockIdx.x & (SEQ / AQ - 1)) * AQ;
    const int bh   = blockIdx.x / (SEQ / AQ);
    const int base = s0 - LOCALB;

    const float* Kp = g_k + (size_t)bh * SEQ * DHEAD;
    const float* Vp = g_v + (size_t)bh * SEQ * DHEAD;

    // stage band rows: 32 rows x 16 f4 x {K,V} = 1024 tasks
    for (int task = threadIdx.x; task < BANDROWS * 16 * 2; task += 512) {
        int which = task >= BANDROWS * 16;
        int tt    = which ? task - BANDROWS * 16 : task;
        int row   = tt >> 4;
        int c4    = (tt & 15) * 4;
        int j     = base + row;
        if (j >= 0) {
            const float* src = (which ? Vp : Kp) + ((size_t)j << 6) + c4;
            float4 val = *(const float4*)src;
            float* dst = which ? &Vb[row][c4] : &Kb[row][c4];
            *(float4*)dst = val;
        }
    }
    __syncthreads();

    const int s = s0 + warp;
    const float* Qp = g_q + (size_t)bh * SEQ * DHEAD + ((size_t)s << 6);

    const float scale = 0.125f;
    float q0 = Qp[lane] * scale;
    float q1 = Qp[lane + 32] * scale;

    const int t = s >> 8;
    const int r = (s >> 4) & 15;
    const int dmax   = min(LOCALB, s);
    const int nFirst = dmax + 1 + max(r - 1, 0);   // <= 31

    // --- logit partials: slot j = band d=j (j<=dmax) else row-stride m=j-dmax+1
    float p[32];
#pragma unroll
    for (int j = 0; j < 32; ++j) {
        float pj = 0.f;
        if (j < nFirst) {                       // warp-uniform branch
            const float* kr = (j <= dmax)
                ? &Kb[warp + LOCALB - j][0]
                : (Kp + ((size_t)(s - 16 * (j - dmax + 1)) << 6));
            pj = q0 * kr[lane] + q1 * kr[lane + 32];
        }
        p[j] = pj;
    }

    // --- butterfly multi-reduce: 31 shuffles; lane n ends with logit n
#pragma unroll
    for (int h = 16; h >= 1; h >>= 1) {
#pragma unroll
        for (int j = 0; j < 16; ++j) {
            if (j < h) {
                float send = (lane & h) ? p[j] : p[j + h];
                float recv = __shfl_xor_sync(FULLMASK, send, h);
                p[j] = ((lane & h) ? p[j + h] : p[j]) + recv;
            }
        }
    }
    const float NEGINF = -CUDART_INF_F;
    float l0 = (lane < nFirst) ? p[0] : NEGINF;

    // --- frame logits (<=3) via shuffle reduce into l1 slots
    float l1 = NEGINF;
    for (int m = 1; m <= t; ++m) {
        const float* kr = Kp + ((size_t)(s - 256 * m) << 6);
        float pp = q0 * kr[lane] + q1 * kr[lane + 32];
        pp += __shfl_xor_sync(FULLMASK, pp, 16);
        pp += __shfl_xor_sync(FULLMASK, pp, 8);
        pp += __shfl_xor_sync(FULLMASK, pp, 4);
        pp += __shfl_xor_sync(FULLMASK, pp, 2);
        pp += __shfl_xor_sync(FULLMASK, pp, 1);
        if (lane == m - 1) l1 = pp;
    }

    // --- softmax
    float mx = fmaxf(l0, l1);
    mx = fmaxf(mx, __shfl_xor_sync(FULLMASK, mx, 16));
    mx = fmaxf(mx, __shfl_xor_sync(FULLMASK, mx, 8));
    mx = fmaxf(mx, __shfl_xor_sync(FULLMASK, mx, 4));
    mx = fmaxf(mx, __shfl_xor_sync(FULLMASK, mx, 2));
    mx = fmaxf(mx, __shfl_xor_sync(FULLMASK, mx, 1));

    float e0 = __expf(l0 - mx);
    float e1 = __expf(l1 - mx);
    float ssum = e0 + e1;
    ssum += __shfl_xor_sync(FULLMASK, ssum, 16);
    ssum += __shfl_xor_sync(FULLMASK, ssum, 8);
    ssum += __shfl_xor_sync(FULLMASK, ssum, 4);
    ssum += __shfl_xor_sync(FULLMASK, ssum, 2);
    ssum += __shfl_xor_sync(FULLMASK, ssum, 1);

    // --- V accumulation
    float acc0 = 0.f, acc1 = 0.f;
#pragma unroll
    for (int n = 0; n < 32; ++n) {
        if (n < nFirst) {                       // warp-uniform
            float pe = __shfl_sync(FULLMASK, e0, n);
            const float* vr = (n <= dmax)
                ? &Vb[warp + LOCALB - n][0]
                : (Vp + ((size_t)(s - 16 * (n - dmax + 1)) << 6));
            acc0 = fmaf(pe, vr[lane], acc0);
            acc1 = fmaf(pe, vr[lane + 32], acc1);
        }
    }
    for (int m = 1; m <= t; ++m) {
        float pe = __shfl_sync(FULLMASK, e1, m - 1);
        const float* vr = Vp + ((size_t)(s - 256 * m) << 6);
        acc0 = fmaf(pe, vr[lane], acc0);
        acc1 = fmaf(pe, vr[lane + 32], acc1);
    }

    float inv = 1.0f / ssum;
    int b = bh >> 3, h = bh & 7;
    size_t o = ((size_t)(b * SEQ + s) * DIM) + h * DHEAD + lane;
    g_att[o]      = acc0 * inv;
    g_att[o + 32] = acc1 * inv;
}

// ---------------------------------------------------------------------------
extern "C" void kernel_launch(void* const* d_in, const int* in_sizes, int n_in,
                              void* d_out, int out_size)
{
    const float* query = (const float*)d_in[0];
    const float* key   = (const float*)d_in[1];
    const float* value = (const float*)d_in[2];
    const float* Wq    = (const float*)d_in[3];
    const float* bq    = (const float*)d_in[4];
    const float* Wk    = (const float*)d_in[5];
    const float* bk    = (const float*)d_in[6];
    const float* Wv    = (const float*)d_in[7];
    const float* bv    = (const float*)d_in[8];
    const float* Wo    = (const float*)d_in[9];
    const float* bo    = (const float*)d_in[10];
    float* out = (float*)d_out;

    // opt-in >48KB dynamic smem (attribute set: not a stream op, capture-safe)
    cudaFuncSetAttribute(proj_qkv_kernel, cudaFuncAttributeMaxDynamicSharedMemorySize, GEMM_SMEM_BYTES);
    cudaFuncSetAttribute(out_proj_kernel, cudaFuncAttributeMaxDynamicSharedMemorySize, GEMM_SMEM_BYTES);

    dim3 blk(256);
    dim3 gridP(DIM / 256, MROWS / 128, 3);   // 2 x 64 x 3
    proj_qkv_kernel<<<gridP, blk, GEMM_SMEM_BYTES>>>(query, key, value, Wq, Wk, Wv, bq, bk, bv);

    dim3 gridA(BATCH * HEADS * (SEQ / AQ));  // 4096 blocks, 512 threads
    sparse_attn_kernel<<<gridA, dim3(512)>>>();

    dim3 gridO(DIM / 256, MROWS / 128);      // 2 x 64
    out_proj_kernel<<<gridO, blk, GEMM_SMEM_BYTES>>>(Wo, bo, out);
}